// round 14
// baseline (speedup 1.0000x reference)
#include <cuda_runtime.h>
#include <cuda_fp16.h>

#define B_ROWS 8192
#define HDIM   1024
#define NACC   2048

// ---------------- device scratch (no allocations allowed) ----------------
// g_Pf: A-fragment-ordered half2 P.  uint idx = ((row16*24 + slice16)*32 + lane)*4 + reg
__device__ __align__(1024) unsigned g_Pf[512 * 24 * 128];          // 6.3 MB
// g_Vf: B-fragment-ordered half2 V.  idx = (((g*16+n128)*12 + k16)*2 + wn)*512 + vg*128 + lane*4 + j
__device__ __align__(1024) unsigned g_Vf[2 * 16 * 12 * 1024];      // 1.57 MB
// g_Wf: B-fragment-ordered half2 U (stage-1 weights).
#define WFS 65536
__device__ __align__(1024) unsigned g_Wf[3 * WFS];                 // 786 KB
// g_Xf / g_Hf: A-fragment-ordered half2 of x and h.
//   idx = ((row16*64 + k16)*32 + lane)*4 + reg ; reg j: row = row16*16 + g4 + (j&1)*8,
//   col pair = k16*16 + 2q + (j>>1)*8 + {0,1}
#define XH_TOTAL (512 * 64 * 128)   // 4,194,304 uints each
#define XH_QUADS (XH_TOTAL / 4)     // 1,048,576 uint4 per array
#define XH_PAIRS (XH_QUADS / 2)     // 524,288 work items (2 k16 per thread) = 1<<19
__device__ __align__(1024) unsigned g_Xf[XH_TOTAL];                // 16.8 MB
__device__ __align__(1024) unsigned g_Hf[XH_TOTAL];                // 16.8 MB
__device__ __align__(16)   float g_bias[4096];

#define VF_TOTAL (2 * 16 * 12 * 1024)
#define WF_TOTAL (3 * WFS)
#define PREP_TOTAL (VF_TOTAL + WF_TOTAL + 2 * XH_PAIRS)

// ---------------- helpers ----------------
__device__ __forceinline__ unsigned pack_h2(float a, float b) {
    __half2 h = __floats2half2_rn(a, b);
    return *reinterpret_cast<unsigned*>(&h);
}
__device__ __forceinline__ float sigmoid_f(float x) {
    float e; asm("ex2.approx.f32 %0, %1;" : "=f"(e) : "f"(-x * 1.4426950408889634f));
    float r; asm("rcp.approx.f32 %0, %1;" : "=f"(r) : "f"(1.0f + e));
    return r;
}
__device__ __forceinline__ float tanh_f(float x) {
    return fmaf(2.0f, sigmoid_f(2.0f * x), -1.0f);
}
__device__ __forceinline__ void mma_f16(float* d, const unsigned* a, const unsigned* b) {
    asm volatile(
        "mma.sync.aligned.m16n8k16.row.col.f32.f16.f16.f32 "
        "{%0,%1,%2,%3}, {%4,%5,%6,%7}, {%8,%9}, {%0,%1,%2,%3};\n"
        : "+f"(d[0]), "+f"(d[1]), "+f"(d[2]), "+f"(d[3])
        : "r"(a[0]), "r"(a[1]), "r"(a[2]), "r"(a[3]), "r"(b[0]), "r"(b[1]));
}
__device__ __forceinline__ void prefetch_l1(const void* p) {
    asm volatile("prefetch.global.L1 [%0];" :: "l"(p));
}
__device__ __forceinline__ void prefetch_l2(const void* p) {
    asm volatile("prefetch.global.L2 [%0];" :: "l"(p));
}

// ---------------- prep: g_Vf + g_Wf + g_Xf/g_Hf + combined bias ----------------
__global__ void prep_kernel(const float* __restrict__ v_x, const float* __restrict__ v_h0,
                            const float* __restrict__ v_h1, const float* __restrict__ u_x,
                            const float* __restrict__ u_h0, const float* __restrict__ u_h1,
                            const float* __restrict__ x,   const float* __restrict__ h,
                            const float* __restrict__ bx,  const float* __restrict__ bh) {
    int idx = blockIdx.x * 256 + threadIdx.x;
    if (idx < 4096) g_bias[idx] = bx[idx] + bh[idx];

    if (idx < VF_TOTAL) {
        int j    = idx & 3;
        int lane = (idx >> 2) & 31;
        int vg   = (idx >> 7) & 3;
        int rest = idx >> 9;
        int wn   = rest & 1;  rest >>= 1;
        int k16  = rest % 12; rest /= 12;
        int n128 = rest & 15;
        int g    = rest >> 4;

        int r    = vg * 4 + j;
        int nt   = r >> 1, kreg = r & 1;
        int g4   = lane >> 2, q = lane & 3;
        int k0   = k16 * 16 + 2 * q + kreg * 8;
        int gate = nt >> 1;
        int s    = n128 * 32 + wn * 16 + (nt & 1) * 8 + g4;

        float v[2];
#pragma unroll
        for (int e = 0; e < 2; e++) {
            int k = k0 + e;
            if (k < 64)       v[e] = v_x[(gate * 1024 + g * 512 + s) * 64 + k];
            else if (k < 128) v[e] = v_h0[(g * 64 + (k - 64)) * 2048 + gate * 512 + s];
            else              v[e] = v_h1[(g * 64 + (k - 128)) * 2048 + gate * 512 + s];
        }
        g_Vf[idx] = pack_h2(v[0], v[1]);
    } else if (idx < VF_TOTAL + WF_TOTAL) {
        int w    = idx - VF_TOTAL;
        int bt   = w / WFS;
        int rem  = w % WFS;
        int j    = rem & 3;
        int lane = (rem >> 2) & 31;
        int vg   = (rem >> 7) & 1;
        int wn   = (rem >> 8) & 3;
        int k16  = rem >> 10;

        int q = lane & 3, g4 = lane >> 2;
        int r = vg * 4 + j, nt = r >> 1, kreg = r & 1;
        int kb = k16 * 16 + 2 * q + kreg * 8;

        unsigned out = 0;
        bool ok = (bt == 0) ? (nt < 2) : (k16 < 32);
        if (ok) {
            int WN = (bt == 0) ? 16 : 32;
            int n  = wn * WN + nt * 8 + g4;
            float v[2];
#pragma unroll
            for (int e = 0; e < 2; e++) {
                int k = kb + e;
                if (bt == 0)      v[e] = u_x[k * 64 + n];
                else if (bt == 1) v[e] = (n < 64) ? u_h0[k * 64 + n]
                                                  : u_h1[(512 + k) * 64 + (n - 64)];
                else              v[e] = (n < 64) ? u_h1[k * 64 + n]
                                                  : u_h0[(512 + k) * 64 + (n - 64)];
            }
            out = pack_h2(v[0], v[1]);
        }
        g_Wf[w] = out;
    } else if (idx < PREP_TOTAL) {
        // x/h -> A-fragment half2: one thread per TWO adjacent k16 (2 uint4, MLP 8)
        int w2  = idx - VF_TOTAL - WF_TOTAL;
        int arr = w2 >> 19;                 // 0 = x, 1 = h  (XH_PAIRS = 1<<19)
        int rem = w2 & (XH_PAIRS - 1);
        int lane  = rem & 31;
        int k8    = (rem >> 5) & 31;        // pair of k16 chunks
        int row16 = rem >> 10;

        int g4 = lane >> 2, q = lane & 3;
        const float* src = arr ? h : x;
        unsigned* dst = arr ? g_Hf : g_Xf;
        const float* rb = src + (size_t)(row16 * 16 + g4) * 1024 + 2 * q;

        float2 v[8];
#pragma unroll
        for (int i = 0; i < 2; i++) {
            int col = (k8 * 2 + i) * 16;
            v[i * 4 + 0] = *(const float2*)(rb + col);
            v[i * 4 + 1] = *(const float2*)(rb + col + 8 * 1024);
            v[i * 4 + 2] = *(const float2*)(rb + col + 8);
            v[i * 4 + 3] = *(const float2*)(rb + col + 8 * 1024 + 8);
        }
#pragma unroll
        for (int i = 0; i < 2; i++) {
            uint4 out;
            out.x = pack_h2(v[i * 4 + 0].x, v[i * 4 + 0].y);
            out.y = pack_h2(v[i * 4 + 1].x, v[i * 4 + 1].y);
            out.z = pack_h2(v[i * 4 + 2].x, v[i * 4 + 2].y);
            out.w = pack_h2(v[i * 4 + 3].x, v[i * 4 + 3].y);
            *(uint4*)(dst + ((size_t)(row16 * 64 + k8 * 2 + i) * 32 + lane) * 4) = out;
        }
    }
}

// ---------------- stage 1: barrier-free fp16 fragment GEMM -> g_Pf ----------------
// M=64 per CTA, 256 thr, 8 warps = 2 wm x 4 wn. All fragments pre-built in gmem.
template<int NT, int NCH>
__device__ __forceinline__ void s1_body(const unsigned* __restrict__ Afrag, int bt, int r0) {
    int t = threadIdx.x, warp = t >> 5, lane = t & 31;
    int wm = warp >> 2, wn = warp & 3;

    const unsigned* Ap[2];
#pragma unroll
    for (int mt = 0; mt < 2; mt++) {
        int row16 = (r0 + wm * 32 + mt * 16) >> 4;
        Ap[mt] = Afrag + (size_t)row16 * (64 * 128) + lane * 4;
    }
    const unsigned* Wp = g_Wf + bt * WFS + wn * 256 + lane * 4;

    float acc[2][NT][4];
#pragma unroll
    for (int i = 0; i < 2; i++)
#pragma unroll
        for (int jn = 0; jn < NT; jn++)
#pragma unroll
            for (int l = 0; l < 4; l++) acc[i][jn][l] = 0.f;

    uint4 a0[2], a1[2], b0[NT / 2], b1[NT / 2];
#pragma unroll
    for (int mt = 0; mt < 2; mt++) a0[mt] = *(const uint4*)(Ap[mt]);
#pragma unroll
    for (int vg = 0; vg < NT / 2; vg++) b0[vg] = *(const uint4*)(Wp + vg * 128);

#pragma unroll
    for (int c = 0; c < NCH; c++) {
        uint4* ac = (c & 1) ? a1 : a0;
        uint4* an = (c & 1) ? a0 : a1;
        uint4* bc = (c & 1) ? b1 : b0;
        uint4* bn = (c & 1) ? b0 : b1;
        if (c + 1 < NCH) {
#pragma unroll
            for (int mt = 0; mt < 2; mt++)
                an[mt] = *(const uint4*)(Ap[mt] + (size_t)(c + 1) * 128);
#pragma unroll
            for (int vg = 0; vg < NT / 2; vg++)
                bn[vg] = *(const uint4*)(Wp + (size_t)(c + 1) * 1024 + vg * 128);
        }
        if (c + 2 < NCH) {                       // L1 prefetch, 2 chunks ahead
#pragma unroll
            for (int mt = 0; mt < 2; mt++)
                prefetch_l1(Ap[mt] + (size_t)(c + 2) * 128);
        }
        const unsigned* bfp = (const unsigned*)bc;
#pragma unroll
        for (int mt = 0; mt < 2; mt++)
#pragma unroll
            for (int nt = 0; nt < NT; nt++)
                mma_f16(acc[mt][nt], (const unsigned*)&ac[mt], bfp + nt * 2);
    }

    // ---- store A-fragment-ordered half2 into g_Pf ----
    const int WN = NT * 8;
#pragma unroll
    for (int mt = 0; mt < 2; mt++) {
        int row16 = (r0 + wm * 32 + mt * 16) >> 4;
#pragma unroll
        for (int nt = 0; nt < NT; nt++) {
            int col = wn * WN + nt * 8;
            int slice;
            if (bt == 0)      slice = col >> 4;
            else if (bt == 1) slice = (col < 64) ? 4 + (col >> 4) : 20 + ((col - 64) >> 4);
            else              slice = (col < 64) ? 8 + (col >> 4) : 16 + ((col - 64) >> 4);
            unsigned p01 = pack_h2(acc[mt][nt][0], acc[mt][nt][1]);
            unsigned p23 = pack_h2(acc[mt][nt][2], acc[mt][nt][3]);
            size_t base = ((size_t)(row16 * 24 + slice) * 32 + lane) * 4 + ((col >> 3) & 1) * 2;
            g_Pf[base]     = p01;
            g_Pf[base + 1] = p23;
            if (bt == 0) {                       // rx duplicated into group-1 block
                g_Pf[base + 12 * 128]     = p01;
                g_Pf[base + 12 * 128 + 1] = p23;
            }
        }
    }
}

__global__ __launch_bounds__(256, 2) void stage1_kernel() {
    int bt = blockIdx.y;
    int r0 = blockIdx.x * 64;
    if (bt == 0)      s1_body<2, 64>(g_Xf, 0, r0);
    else if (bt == 1) s1_body<4, 32>(g_Hf, 1, r0);
    else              s1_body<4, 32>(g_Hf + 32 * 128, 2, r0);
}

// ---------------- stage 2: barrier-free fp16 fragment GEMM + fused gate epilogue ----------------
__global__ __launch_bounds__(256, 2) void stage2_kernel(const float* __restrict__ cin,
                                                        float* __restrict__ out) {
    int r0 = blockIdx.x * 128, n128 = blockIdx.y, g = blockIdx.z;
    int s0 = n128 * 32;
    int t = threadIdx.x, warp = t >> 5, lane = t & 31, g4 = lane >> 2, q = lane & 3;
    int wm = warp & 3, wn = warp >> 2;          // 4 m-warps x 2 n-warps; warp tile 32x64

    const unsigned* Ap = g_Pf + ((size_t)((r0 >> 4) + wm * 2) * 24 + g * 12) * 128 + lane * 4;
    const unsigned* Bp = g_Vf + (size_t)(g * 16 + n128) * 12 * 1024 + wn * 512 + lane * 4;

    // warm L2 with this thread's cin lines (overlaps DRAM fetch with the mainloop)
    {
        const float* cb = cin + (size_t)(r0 + wm * 32 + g4) * HDIM
                              + g * 512 + s0 + wn * 16 + 2 * q;
#pragma unroll
        for (int mt = 0; mt < 2; mt++)
#pragma unroll
            for (int rh = 0; rh < 2; rh++) {
                prefetch_l2(cb + (size_t)(mt * 16 + rh * 8) * HDIM);
                prefetch_l2(cb + (size_t)(mt * 16 + rh * 8) * HDIM + 8);
            }
    }

    float acc[2][8][4];
#pragma unroll
    for (int i = 0; i < 2; i++)
#pragma unroll
        for (int jn = 0; jn < 8; jn++)
#pragma unroll
            for (int l = 0; l < 4; l++) acc[i][jn][l] = 0.f;

    uint4 a0[2], a1[2], b0[4], b1[4];
    a0[0] = *(const uint4*)(Ap);
    a0[1] = *(const uint4*)(Ap + 24 * 128);
#pragma unroll
    for (int vg = 0; vg < 4; vg++) b0[vg] = *(const uint4*)(Bp + vg * 128);

#pragma unroll
    for (int c = 0; c < 12; c++) {
        uint4* ac = (c & 1) ? a1 : a0;
        uint4* an = (c & 1) ? a0 : a1;
        uint4* bc = (c & 1) ? b1 : b0;
        uint4* bn = (c & 1) ? b0 : b1;
        if (c < 11) {                            // prefetch next chunk (A + B) into regs
            an[0] = *(const uint4*)(Ap + (size_t)(c + 1) * 128);
            an[1] = *(const uint4*)(Ap + (size_t)(c + 1) * 128 + 24 * 128);
#pragma unroll
            for (int vg = 0; vg < 4; vg++)
                bn[vg] = *(const uint4*)(Bp + (size_t)(c + 1) * 1024 + vg * 128);
        }
        if (c < 10) {                            // L1 prefetch, 2 chunks ahead (reg-free)
            prefetch_l1(Ap + (size_t)(c + 2) * 128);
            prefetch_l1(Ap + (size_t)(c + 2) * 128 + 24 * 128);
#pragma unroll
            for (int vg = 0; vg < 4; vg++)
                prefetch_l1(Bp + (size_t)(c + 2) * 1024 + vg * 128);
        }
        const unsigned* af0 = (const unsigned*)&ac[0];
        const unsigned* af1 = (const unsigned*)&ac[1];
        const unsigned* bfp = (const unsigned*)bc;
#pragma unroll
        for (int nt = 0; nt < 8; nt++) {
            mma_f16(acc[0][nt], af0, bfp + nt * 2);
            mma_f16(acc[1][nt], af1, bfp + nt * 2);
        }
    }

    // ---- fused epilogue: gate = nt>>1, s = s0 + wn*16 + (nt&1)*8 + 2q + e ----
    float* out_h = out;
    float* out_c = out + (size_t)B_ROWS * HDIM;
#pragma unroll
    for (int mt = 0; mt < 2; mt++) {
#pragma unroll
        for (int rh = 0; rh < 2; rh++) {
            int row = r0 + wm * 32 + mt * 16 + g4 + rh * 8;
#pragma unroll
            for (int sh = 0; sh < 2; sh++) {
                int sbase = s0 + wn * 16 + sh * 8 + 2 * q;
                float hv2[2], cv2[2];
                float2 cvv = *(const float2*)&cin[(size_t)row * HDIM + g * 512 + sbase];
                float cvin[2] = { cvv.x, cvv.y };
#pragma unroll
                for (int e = 0; e < 2; e++) {
                    int s = sbase + e;
                    int l = rh * 2 + e;
                    float fp = acc[mt][0 + sh][l] + g_bias[0 * 1024 + g * 512 + s];
                    float ip = acc[mt][2 + sh][l] + g_bias[1 * 1024 + g * 512 + s];
                    float np = acc[mt][4 + sh][l] + g_bias[2 * 1024 + g * 512 + s];
                    float op = acc[mt][6 + sh][l] + g_bias[3 * 1024 + g * 512 + s];
                    float fg = sigmoid_f(fp), ig = sigmoid_f(ip), og = sigmoid_f(op);
                    float ng = tanh_f(np);
                    float cn = fg * cvin[e] + ig * ng;
                    hv2[e] = og * tanh_f(cn);
                    cv2[e] = cn;
                }
                size_t off = (size_t)row * HDIM + g * 512 + sbase;
                *(float2*)&out_h[off] = make_float2(hv2[0], hv2[1]);
                *(float2*)&out_c[off] = make_float2(cv2[0], cv2[1]);
            }
        }
    }
}

// ---------------- launch ----------------
extern "C" void kernel_launch(void* const* d_in, const int* in_sizes, int n_in,
                              void* d_out, int out_size) {
    const float* x    = (const float*)d_in[0];
    const float* h    = (const float*)d_in[1];
    const float* c    = (const float*)d_in[2];
    const float* u_x  = (const float*)d_in[3];
    const float* v_x  = (const float*)d_in[4];
    const float* u_h0 = (const float*)d_in[5];
    const float* v_h0 = (const float*)d_in[6];
    const float* u_h1 = (const float*)d_in[7];
    const float* v_h1 = (const float*)d_in[8];
    const float* bx   = (const float*)d_in[9];
    const float* bh   = (const float*)d_in[10];

    int prep_blocks = (PREP_TOTAL + 255) / 256;
    prep_kernel<<<prep_blocks, 256>>>(v_x, v_h0, v_h1, u_x, u_h0, u_h1, x, h, bx, bh);
    stage1_kernel<<<dim3(128, 3), 256>>>();
    stage2_kernel<<<dim3(64, 16, 2), 256>>>(c, (float*)d_out);
}

// round 15
// speedup vs baseline: 1.2323x; 1.2323x over previous
#include <cuda_runtime.h>
#include <cuda_fp16.h>

#define B_ROWS 8192
#define HDIM   1024
#define NACC   2048

// ---------------- device scratch (no allocations allowed) ----------------
// g_Pf: A-fragment-ordered half2 P.  uint idx = ((row16*24 + slice16)*32 + lane)*4 + reg
__device__ __align__(1024) unsigned g_Pf[512 * 24 * 128];          // 6.3 MB
// g_Vf: B-fragment-ordered half2 V.  idx = (((g*16+n128)*12 + k16)*2 + wn)*512 + vg*128 + lane*4 + j
__device__ __align__(1024) unsigned g_Vf[2 * 16 * 12 * 1024];      // 1.57 MB
// g_Wf: B-fragment-ordered half2 U (stage-1 weights).
#define WFS 65536
__device__ __align__(1024) unsigned g_Wf[3 * WFS];                 // 786 KB
// g_Xf / g_Hf: A-fragment-ordered half2 of x and h.
//   idx = ((row16*64 + k16)*32 + lane)*4 + reg ; reg j: row = row16*16 + g4 + (j&1)*8,
//   col pair = k16*16 + 2q + (j>>1)*8 + {0,1}
#define XH_TOTAL (512 * 64 * 128)   // 4,194,304 uints each
#define XH_QUADS (XH_TOTAL / 4)     // 1,048,576 uint4 per array
__device__ __align__(1024) unsigned g_Xf[XH_TOTAL];                // 16.8 MB
__device__ __align__(1024) unsigned g_Hf[XH_TOTAL];                // 16.8 MB
__device__ __align__(16)   float g_bias[4096];

#define VF_TOTAL (2 * 16 * 12 * 1024)
#define WF_TOTAL (3 * WFS)
#define PREP_TOTAL (VF_TOTAL + WF_TOTAL + 2 * XH_QUADS)

// ---------------- helpers ----------------
__device__ __forceinline__ unsigned pack_h2(float a, float b) {
    __half2 h = __floats2half2_rn(a, b);
    return *reinterpret_cast<unsigned*>(&h);
}
__device__ __forceinline__ float sigmoid_f(float x) {
    float e; asm("ex2.approx.f32 %0, %1;" : "=f"(e) : "f"(-x * 1.4426950408889634f));
    float r; asm("rcp.approx.f32 %0, %1;" : "=f"(r) : "f"(1.0f + e));
    return r;
}
__device__ __forceinline__ float tanh_f(float x) {
    return fmaf(2.0f, sigmoid_f(2.0f * x), -1.0f);
}
__device__ __forceinline__ void mma_f16(float* d, const unsigned* a, const unsigned* b) {
    asm volatile(
        "mma.sync.aligned.m16n8k16.row.col.f32.f16.f16.f32 "
        "{%0,%1,%2,%3}, {%4,%5,%6,%7}, {%8,%9}, {%0,%1,%2,%3};\n"
        : "+f"(d[0]), "+f"(d[1]), "+f"(d[2]), "+f"(d[3])
        : "r"(a[0]), "r"(a[1]), "r"(a[2]), "r"(a[3]), "r"(b[0]), "r"(b[1]));
}
__device__ __forceinline__ void cp_async16_sh(unsigned* smem_dst, const unsigned* gsrc) {
    unsigned d = (unsigned)__cvta_generic_to_shared(smem_dst);
    asm volatile("cp.async.cg.shared.global [%0], [%1], 16;" :: "r"(d), "l"(gsrc));
}

// ---------------- prep: g_Vf + g_Wf + g_Xf/g_Hf + combined bias ----------------
__global__ void prep_kernel(const float* __restrict__ v_x, const float* __restrict__ v_h0,
                            const float* __restrict__ v_h1, const float* __restrict__ u_x,
                            const float* __restrict__ u_h0, const float* __restrict__ u_h1,
                            const float* __restrict__ x,   const float* __restrict__ h,
                            const float* __restrict__ bx,  const float* __restrict__ bh) {
    int idx = blockIdx.x * 256 + threadIdx.x;
    if (idx < 4096) g_bias[idx] = bx[idx] + bh[idx];

    if (idx < VF_TOTAL) {
        int j    = idx & 3;
        int lane = (idx >> 2) & 31;
        int vg   = (idx >> 7) & 3;
        int rest = idx >> 9;
        int wn   = rest & 1;  rest >>= 1;
        int k16  = rest % 12; rest /= 12;
        int n128 = rest & 15;
        int g    = rest >> 4;

        int r    = vg * 4 + j;
        int nt   = r >> 1, kreg = r & 1;
        int g4   = lane >> 2, q = lane & 3;
        int k0   = k16 * 16 + 2 * q + kreg * 8;
        int gate = nt >> 1;
        int s    = n128 * 32 + wn * 16 + (nt & 1) * 8 + g4;

        float v[2];
#pragma unroll
        for (int e = 0; e < 2; e++) {
            int k = k0 + e;
            if (k < 64)       v[e] = v_x[(gate * 1024 + g * 512 + s) * 64 + k];
            else if (k < 128) v[e] = v_h0[(g * 64 + (k - 64)) * 2048 + gate * 512 + s];
            else              v[e] = v_h1[(g * 64 + (k - 128)) * 2048 + gate * 512 + s];
        }
        g_Vf[idx] = pack_h2(v[0], v[1]);
    } else if (idx < VF_TOTAL + WF_TOTAL) {
        int w    = idx - VF_TOTAL;
        int bt   = w / WFS;
        int rem  = w % WFS;
        int j    = rem & 3;
        int lane = (rem >> 2) & 31;
        int vg   = (rem >> 7) & 1;
        int wn   = (rem >> 8) & 3;
        int k16  = rem >> 10;

        int q = lane & 3, g4 = lane >> 2;
        int r = vg * 4 + j, nt = r >> 1, kreg = r & 1;
        int kb = k16 * 16 + 2 * q + kreg * 8;

        unsigned out = 0;
        bool ok = (bt == 0) ? (nt < 2) : (k16 < 32);
        if (ok) {
            int WN = (bt == 0) ? 16 : 32;
            int n  = wn * WN + nt * 8 + g4;
            float v[2];
#pragma unroll
            for (int e = 0; e < 2; e++) {
                int k = kb + e;
                if (bt == 0)      v[e] = u_x[k * 64 + n];
                else if (bt == 1) v[e] = (n < 64) ? u_h0[k * 64 + n]
                                                  : u_h1[(512 + k) * 64 + (n - 64)];
                else              v[e] = (n < 64) ? u_h1[k * 64 + n]
                                                  : u_h0[(512 + k) * 64 + (n - 64)];
            }
            out = pack_h2(v[0], v[1]);
        }
        g_Wf[w] = out;
    } else if (idx < PREP_TOTAL) {
        // x/h -> A-fragment half2, one thread per uint4 (full lane fragment)
        int w2  = idx - VF_TOTAL - WF_TOTAL;
        int arr = w2 >> 20;                 // 0 = x, 1 = h  (XH_QUADS = 1<<20)
        int rem = w2 & (XH_QUADS - 1);
        int lane  = rem & 31;
        int k16   = (rem >> 5) & 63;
        int row16 = rem >> 11;

        int g4 = lane >> 2, q = lane & 3;
        const float* src = arr ? h : x;
        const float* base = src + (size_t)(row16 * 16 + g4) * 1024 + k16 * 16 + 2 * q;

        float2 v0 = *(const float2*)(base);                 // row g4,   cols 2q..2q+1
        float2 v1 = *(const float2*)(base + 8 * 1024);      // row g4+8
        float2 v2 = *(const float2*)(base + 8);             // row g4,   cols +8
        float2 v3 = *(const float2*)(base + 8 * 1024 + 8);  // row g4+8, cols +8

        uint4 out;
        out.x = pack_h2(v0.x, v0.y);
        out.y = pack_h2(v1.x, v1.y);
        out.z = pack_h2(v2.x, v2.y);
        out.w = pack_h2(v3.x, v3.y);
        unsigned* dst = arr ? g_Hf : g_Xf;
        *(uint4*)(dst + (size_t)rem * 4) = out;
    }
}

// ---------------- stage 1: barrier-free fp16 fragment GEMM -> g_Pf ----------------
// M=64 per CTA, 256 thr, 8 warps = 2 wm x 4 wn. All fragments pre-built in gmem.
template<int NT, int NCH>
__device__ __forceinline__ void s1_body(const unsigned* __restrict__ Afrag, int bt, int r0) {
    int t = threadIdx.x, warp = t >> 5, lane = t & 31;
    int wm = warp >> 2, wn = warp & 3;

    const unsigned* Ap[2];
#pragma unroll
    for (int mt = 0; mt < 2; mt++) {
        int row16 = (r0 + wm * 32 + mt * 16) >> 4;
        Ap[mt] = Afrag + (size_t)row16 * (64 * 128) + lane * 4;
    }
    const unsigned* Wp = g_Wf + bt * WFS + wn * 256 + lane * 4;

    float acc[2][NT][4];
#pragma unroll
    for (int i = 0; i < 2; i++)
#pragma unroll
        for (int jn = 0; jn < NT; jn++)
#pragma unroll
            for (int l = 0; l < 4; l++) acc[i][jn][l] = 0.f;

    uint4 a0[2], a1[2], b0[NT / 2], b1[NT / 2];
#pragma unroll
    for (int mt = 0; mt < 2; mt++) a0[mt] = *(const uint4*)(Ap[mt]);
#pragma unroll
    for (int vg = 0; vg < NT / 2; vg++) b0[vg] = *(const uint4*)(Wp + vg * 128);

#pragma unroll
    for (int c = 0; c < NCH; c++) {
        uint4* ac = (c & 1) ? a1 : a0;
        uint4* an = (c & 1) ? a0 : a1;
        uint4* bc = (c & 1) ? b1 : b0;
        uint4* bn = (c & 1) ? b0 : b1;
        if (c + 1 < NCH) {
#pragma unroll
            for (int mt = 0; mt < 2; mt++)
                an[mt] = *(const uint4*)(Ap[mt] + (size_t)(c + 1) * 128);
#pragma unroll
            for (int vg = 0; vg < NT / 2; vg++)
                bn[vg] = *(const uint4*)(Wp + (size_t)(c + 1) * 1024 + vg * 128);
        }
        const unsigned* bfp = (const unsigned*)bc;
#pragma unroll
        for (int mt = 0; mt < 2; mt++)
#pragma unroll
            for (int nt = 0; nt < NT; nt++)
                mma_f16(acc[mt][nt], (const unsigned*)&ac[mt], bfp + nt * 2);
    }

    // ---- store A-fragment-ordered half2 into g_Pf ----
    const int WN = NT * 8;
#pragma unroll
    for (int mt = 0; mt < 2; mt++) {
        int row16 = (r0 + wm * 32 + mt * 16) >> 4;
#pragma unroll
        for (int nt = 0; nt < NT; nt++) {
            int col = wn * WN + nt * 8;
            int slice;
            if (bt == 0)      slice = col >> 4;
            else if (bt == 1) slice = (col < 64) ? 4 + (col >> 4) : 20 + ((col - 64) >> 4);
            else              slice = (col < 64) ? 8 + (col >> 4) : 16 + ((col - 64) >> 4);
            unsigned p01 = pack_h2(acc[mt][nt][0], acc[mt][nt][1]);
            unsigned p23 = pack_h2(acc[mt][nt][2], acc[mt][nt][3]);
            size_t base = ((size_t)(row16 * 24 + slice) * 32 + lane) * 4 + ((col >> 3) & 1) * 2;
            g_Pf[base]     = p01;
            g_Pf[base + 1] = p23;
            if (bt == 0) {                       // rx duplicated into group-1 block
                g_Pf[base + 12 * 128]     = p01;
                g_Pf[base + 12 * 128 + 1] = p23;
            }
        }
    }
}

__global__ __launch_bounds__(256, 2) void stage1_kernel() {
    int bt = blockIdx.y;
    int r0 = blockIdx.x * 64;
    if (bt == 0)      s1_body<2, 64>(g_Xf, 0, r0);
    else if (bt == 1) s1_body<4, 32>(g_Hf, 1, r0);
    else              s1_body<4, 32>(g_Hf + 32 * 128, 2, r0);
}

// ---------------- stage 2: B in SMEM (loaded once), A fragment-direct, fused epilogue ----------------
#define S2_SMEM 49152   // 12 chunks x 1024 uints x 4B = full B tile

__global__ __launch_bounds__(256, 2) void stage2_kernel(const float* __restrict__ cin,
                                                        float* __restrict__ out) {
    extern __shared__ unsigned Bs[];

    int r0 = blockIdx.x * 128, n128 = blockIdx.y, g = blockIdx.z;
    int s0 = n128 * 32;
    int t = threadIdx.x, warp = t >> 5, lane = t & 31, g4 = lane >> 2, q = lane & 3;
    int wm = warp & 3, wn = warp >> 2;          // 4 m-warps x 2 n-warps; warp tile 32x64

    const unsigned* Ap = g_Pf + ((size_t)((r0 >> 4) + wm * 2) * 24 + g * 12) * 128 + lane * 4;
    const unsigned* Bg = g_Vf + (size_t)(g * 16 + n128) * 12 * 1024;

    // ---- load the whole B tile into smem once (cp.async, single barrier) ----
#pragma unroll
    for (int i = 0; i < 12; i++)
        cp_async16_sh(Bs + (size_t)(i * 256 + t) * 4, Bg + (size_t)(i * 256 + t) * 4);
    asm volatile("cp.async.commit_group;" ::: "memory");

    float acc[2][8][4];
#pragma unroll
    for (int i = 0; i < 2; i++)
#pragma unroll
        for (int jn = 0; jn < 8; jn++)
#pragma unroll
            for (int l = 0; l < 4; l++) acc[i][jn][l] = 0.f;

    // A chunk-0 loads overlap the B smem fill
    uint4 a0[2], a1[2], b0[4], b1[4];
    a0[0] = *(const uint4*)(Ap);
    a0[1] = *(const uint4*)(Ap + 24 * 128);

    asm volatile("cp.async.wait_group 0;" ::: "memory");
    __syncthreads();

    const unsigned* Bp = Bs + wn * 512 + lane * 4;
#pragma unroll
    for (int vg = 0; vg < 4; vg++) b0[vg] = *(const uint4*)(Bp + vg * 128);

#pragma unroll
    for (int c = 0; c < 12; c++) {
        uint4* ac = (c & 1) ? a1 : a0;
        uint4* an = (c & 1) ? a0 : a1;
        uint4* bc = (c & 1) ? b1 : b0;
        uint4* bn = (c & 1) ? b0 : b1;
        if (c < 11) {                            // prefetch next chunk: A from L2, B from smem
            an[0] = *(const uint4*)(Ap + (size_t)(c + 1) * 128);
            an[1] = *(const uint4*)(Ap + (size_t)(c + 1) * 128 + 24 * 128);
#pragma unroll
            for (int vg = 0; vg < 4; vg++)
                bn[vg] = *(const uint4*)(Bp + (size_t)(c + 1) * 1024 + vg * 128);
        }
        const unsigned* af0 = (const unsigned*)&ac[0];
        const unsigned* af1 = (const unsigned*)&ac[1];
        const unsigned* bfp = (const unsigned*)bc;
#pragma unroll
        for (int nt = 0; nt < 8; nt++) {
            mma_f16(acc[0][nt], af0, bfp + nt * 2);
            mma_f16(acc[1][nt], af1, bfp + nt * 2);
        }
    }

    // ---- fused epilogue: gate = nt>>1, s = s0 + wn*16 + (nt&1)*8 + 2q + e ----
    float* out_h = out;
    float* out_c = out + (size_t)B_ROWS * HDIM;
#pragma unroll
    for (int mt = 0; mt < 2; mt++) {
#pragma unroll
        for (int rh = 0; rh < 2; rh++) {
            int row = r0 + wm * 32 + mt * 16 + g4 + rh * 8;
#pragma unroll
            for (int sh = 0; sh < 2; sh++) {
                int sbase = s0 + wn * 16 + sh * 8 + 2 * q;
                float hv2[2], cv2[2];
                float2 cvv = *(const float2*)&cin[(size_t)row * HDIM + g * 512 + sbase];
                float cvin[2] = { cvv.x, cvv.y };
#pragma unroll
                for (int e = 0; e < 2; e++) {
                    int s = sbase + e;
                    int l = rh * 2 + e;
                    float fp = acc[mt][0 + sh][l] + g_bias[0 * 1024 + g * 512 + s];
                    float ip = acc[mt][2 + sh][l] + g_bias[1 * 1024 + g * 512 + s];
                    float np = acc[mt][4 + sh][l] + g_bias[2 * 1024 + g * 512 + s];
                    float op = acc[mt][6 + sh][l] + g_bias[3 * 1024 + g * 512 + s];
                    float fg = sigmoid_f(fp), ig = sigmoid_f(ip), og = sigmoid_f(op);
                    float ng = tanh_f(np);
                    float cn = fg * cvin[e] + ig * ng;
                    hv2[e] = og * tanh_f(cn);
                    cv2[e] = cn;
                }
                size_t off = (size_t)row * HDIM + g * 512 + sbase;
                *(float2*)&out_h[off] = make_float2(hv2[0], hv2[1]);
                *(float2*)&out_c[off] = make_float2(cv2[0], cv2[1]);
            }
        }
    }
}

// ---------------- launch ----------------
extern "C" void kernel_launch(void* const* d_in, const int* in_sizes, int n_in,
                              void* d_out, int out_size) {
    const float* x    = (const float*)d_in[0];
    const float* h    = (const float*)d_in[1];
    const float* c    = (const float*)d_in[2];
    const float* u_x  = (const float*)d_in[3];
    const float* v_x  = (const float*)d_in[4];
    const float* u_h0 = (const float*)d_in[5];
    const float* v_h0 = (const float*)d_in[6];
    const float* u_h1 = (const float*)d_in[7];
    const float* v_h1 = (const float*)d_in[8];
    const float* bx   = (const float*)d_in[9];
    const float* bh   = (const float*)d_in[10];

    cudaFuncSetAttribute(stage2_kernel, cudaFuncAttributeMaxDynamicSharedMemorySize, S2_SMEM);

    int prep_blocks = (PREP_TOTAL + 255) / 256;
    prep_kernel<<<prep_blocks, 256>>>(v_x, v_h0, v_h1, u_x, u_h0, u_h1, x, h, bx, bh);
    stage1_kernel<<<dim3(128, 3), 256>>>();
    stage2_kernel<<<dim3(64, 16, 2), 256, S2_SMEM>>>(c, (float*)d_out);
}